// round 11
// baseline (speedup 1.0000x reference)
#include <cuda_runtime.h>
#include <cuda_bf16.h>

// Scratch: __device__ globals (no allocations allowed).
// g_deg starts zero (static init) and is re-zeroed by k_sred each call.
#define MAXN 100352   // >= 100,000 nodes, multiple of 1024 (= 98 blocks * 256 * 4)
#define HID  128

__device__ float g_deg[MAXN];   // edge-degree (zeroed by previous k_sred; +1 self loop in rsqrt)
__device__ float g_dinv[MAXN];  // (deg+1)^-1/2
__device__ float g_dxv[MAXN];   // dinv * x
__device__ float g_u[MAXN];     // u[c] = sum dinv[r]*x[r]   (seeded w/ self loop)
__device__ float g_t[MAXN];     // t[r] = sum dinv[c]        (seeded w/ self loop)
__device__ float g_A[2];        // A+ , A-
__device__ int   g_ctr;         // last-block counter (zeroed by k_dinv)

// ---------------------------------------------------------------------------
// 1) degree scatter over destinations (8 edges/thread)
__global__ void __launch_bounds__(256) k_deg(const int* __restrict__ col, int E) {
    int t = blockIdx.x * blockDim.x + threadIdx.x;
    int i = t * 8;
    if (i + 7 < E) {
        int c[8];
        *reinterpret_cast<int4*>(c)     = *reinterpret_cast<const int4*>(col + i);
        *reinterpret_cast<int4*>(c + 4) = *reinterpret_cast<const int4*>(col + i + 4);
        #pragma unroll
        for (int j = 0; j < 8; ++j) atomicAdd(&g_deg[c[j]], 1.0f);
    } else if (i < E) {
        for (; i < E; ++i) atomicAdd(&g_deg[col[i]], 1.0f);
    }
}

// 2) dinv = rsqrt(deg+1); dxv = dinv*x; seed u,t with self-loop; zero A & ctr
__global__ void k_dinv(const float* __restrict__ x, int n) {
    int i4 = blockIdx.x * blockDim.x + threadIdx.x;
    int i = i4 * 4;
    if (i + 3 < n) {
        float4 d = *reinterpret_cast<const float4*>(g_deg + i);
        float4 xv = *reinterpret_cast<const float4*>(x + i);
        float4 di, dx;
        di.x = rsqrtf(d.x + 1.0f); di.y = rsqrtf(d.y + 1.0f);
        di.z = rsqrtf(d.z + 1.0f); di.w = rsqrtf(d.w + 1.0f);
        dx.x = di.x * xv.x; dx.y = di.y * xv.y;
        dx.z = di.z * xv.z; dx.w = di.w * xv.w;
        *reinterpret_cast<float4*>(g_dinv + i) = di;
        *reinterpret_cast<float4*>(g_dxv + i)  = dx;
        *reinterpret_cast<float4*>(g_u + i)    = dx;  // self loop: dinv*x
        *reinterpret_cast<float4*>(g_t + i)    = di;  // self loop: dinv
    } else {
        for (; i < n; ++i) {
            float di = rsqrtf(g_deg[i] + 1.0f);
            float dx = di * x[i];
            g_dinv[i] = di; g_dxv[i] = dx; g_u[i] = dx; g_t[i] = di;
        }
    }
    if (i4 == 0) { g_A[0] = 0.0f; g_A[1] = 0.0f; g_ctr = 0; }
}

// 3) edge pass: u[c] += dxv[r]; t[r] += dinv[c]   (16 edges/thread, 32 gathers in flight)
#define EPT 16
__global__ void __launch_bounds__(256) k_edge(const int* __restrict__ row,
                                              const int* __restrict__ col, int E) {
    int t = blockIdx.x * blockDim.x + threadIdx.x;
    int i = t * EPT;
    if (i + EPT - 1 < E) {
        int r[EPT], c[EPT];
        #pragma unroll
        for (int q = 0; q < EPT / 4; ++q) {
            *reinterpret_cast<int4*>(r + q * 4) = *reinterpret_cast<const int4*>(row + i + q * 4);
            *reinterpret_cast<int4*>(c + q * 4) = *reinterpret_cast<const int4*>(col + i + q * 4);
        }
        float dx[EPT], dc[EPT];
        #pragma unroll
        for (int j = 0; j < EPT; ++j) {
            dx[j] = __ldg(&g_dxv[r[j]]);
            dc[j] = __ldg(&g_dinv[c[j]]);
        }
        #pragma unroll
        for (int j = 0; j < EPT; ++j) {
            atomicAdd(&g_u[c[j]], dx[j]);
            atomicAdd(&g_t[r[j]], dc[j]);
        }
    } else if (i < E) {
        int iend = min(i + EPT, E);
        for (; i < iend; ++i) {
            int r = row[i], c = col[i];
            atomicAdd(&g_u[c], g_dxv[r]);
            atomicAdd(&g_t[r], g_dinv[c]);
        }
    }
}

// 4) fused: A+/A- reduction, re-zero g_deg for the next call, then last block
//    computes v[k] = W1k*(W1k>0 ? A+ : A-) (exact for b1k==0; fallback loop
//    otherwise) and the 128->400 GEMV.  Fence executed by ONE thread per block.
__global__ void __launch_bounds__(256) k_sred(const float* __restrict__ W1,
                                              const float* __restrict__ b1,
                                              const float* __restrict__ W2,
                                              const float* __restrict__ b2,
                                              float* __restrict__ out,
                                              int n, int od) {
    int tid = threadIdx.x;
    float ap = 0.0f, am = 0.0f;
    int i4 = blockIdx.x * blockDim.x + tid;
    int i = i4 * 4;
    if (i + 3 < n) {
        float4 di = *reinterpret_cast<const float4*>(g_dinv + i);
        float4 u  = *reinterpret_cast<const float4*>(g_u + i);
        float4 tt = *reinterpret_cast<const float4*>(g_t + i);
        float s0 = di.x * u.x, w0 = di.x * tt.x;
        float s1 = di.y * u.y, w1 = di.y * tt.y;
        float s2 = di.z * u.z, w2 = di.z * tt.z;
        float s3 = di.w * u.w, w3 = di.w * tt.w;
        if (s0 > 0.0f) ap += w0 * s0; else am += w0 * s0;
        if (s1 > 0.0f) ap += w1 * s1; else am += w1 * s1;
        if (s2 > 0.0f) ap += w2 * s2; else am += w2 * s2;
        if (s3 > 0.0f) ap += w3 * s3; else am += w3 * s3;
    } else {
        for (int q = i; q < n; ++q) {
            float di = g_dinv[q];
            float s = di * g_u[q], w = di * g_t[q];
            if (s > 0.0f) ap += w * s; else am += w * s;
        }
    }
    // re-zero g_deg for the next invocation (grid exactly covers MAXN/4)
    if (i + 3 < MAXN)
        *reinterpret_cast<float4*>(g_deg + i) = make_float4(0.f, 0.f, 0.f, 0.f);

    #pragma unroll
    for (int off = 16; off; off >>= 1) {
        ap += __shfl_xor_sync(0xffffffffu, ap, off);
        am += __shfl_xor_sync(0xffffffffu, am, off);
    }
    if ((tid & 31) == 0) {
        atomicAdd(&g_A[0], ap);
        atomicAdd(&g_A[1], am);
    }
    __syncthreads();                 // block's atomics issued
    __shared__ int sLast;
    if (tid == 0) {
        __threadfence();             // ONE fence per block (98 total), cheap
        sLast = (atomicAdd(&g_ctr, 1) == gridDim.x - 1);
    }
    __syncthreads();
    if (!sLast) return;

    // ---- final block: v[k] then GEMV out[o] = (1/n)*sum_k v[k]*W2[k,o] + b2[o]
    __shared__ float vs[HID];
    float Ap = *((volatile float*)&g_A[0]);
    float Am = *((volatile float*)&g_A[1]);
    if (tid < HID) {
        float w1k = W1[tid];
        float b1k = b1[tid];
        float v;
        if (b1k == 0.0f) {
            v = w1k * (w1k > 0.0f ? Ap : Am);   // exact ReLU factorization
        } else {
            // generic fallback (never hit with b1 = 0)
            v = 0.0f;
            for (int q = 0; q < n; ++q) {
                float di = g_dinv[q];
                float s = di * g_u[q], w = di * g_t[q];
                v += w * fmaxf(s * w1k + b1k, 0.0f);
            }
        }
        vs[tid] = v;
    }
    __syncthreads();
    float inv_n = 1.0f / (float)n;
    for (int o = tid; o < od; o += 256) {
        float a = 0.0f;
        #pragma unroll 8
        for (int kk = 0; kk < HID; ++kk) {
            a += vs[kk] * W2[kk * od + o];   // coalesced over o
        }
        out[o] = a * inv_n + b2[o];
    }
}

// ---------------------------------------------------------------------------
extern "C" void kernel_launch(void* const* d_in, const int* in_sizes, int n_in,
                              void* d_out, int out_size) {
    const float* x   = (const float*)d_in[0];   // [N]
    const int*   ei  = (const int*)d_in[1];     // [2, E] row-major
    const float* W1  = (const float*)d_in[2];   // [128]
    const float* b1  = (const float*)d_in[3];   // [128]
    const float* W2  = (const float*)d_in[4];   // [128, OUT]
    const float* b2  = (const float*)d_in[5];   // [OUT]
    float* out = (float*)d_out;

    int N = in_sizes[0];
    int E = in_sizes[1] / 2;
    int OD = in_sizes[5];
    const int* row = ei;
    const int* col = ei + E;

    int tb = 256;
    int nt8 = (E + 7) / 8;
    k_deg<<<(nt8 + tb - 1) / tb, tb>>>(col, E);

    int n4 = (N + 3) / 4;
    int nblk = (n4 + tb - 1) / tb;   // 98 blocks: covers MAXN exactly (98*256*4)
    k_dinv<<<nblk, tb>>>(x, N);

    int ntE = (E + EPT - 1) / EPT;
    k_edge<<<(ntE + tb - 1) / tb, tb>>>(row, col, E);

    k_sred<<<nblk, tb>>>(W1, b1, W2, b2, out, N, OD);
}

// round 12
// speedup vs baseline: 1.0868x; 1.0868x over previous
#include <cuda_runtime.h>
#include <cuda_bf16.h>

// Scratch: __device__ globals (no allocations allowed).
// g_deg starts zero (static init) and is re-zeroed by k_sred each call.
#define MAXN 100352   // >= 100,000 nodes, multiple of 1024
#define HID  128

__device__ float g_deg[MAXN];   // edge-degree (zeroed by previous k_sred)
__device__ float g_dinv[MAXN];  // (deg+1)^-1/2
__device__ float g_dxv[MAXN];   // dinv * x
__device__ float g_u[MAXN];     // u[c] = sum dinv[r]*x[r]   (seeded w/ self loop)
__device__ float g_t[MAXN];     // t[r] = sum dinv[c]        (seeded w/ self loop)
__device__ float g_A[2];        // A+ , A-

// ---------------------------------------------------------------------------
// 1) degree scatter over destinations (16 edges/thread, streaming index loads)
#define DPT 16
__global__ void __launch_bounds__(256) k_deg(const int* __restrict__ col, int E) {
    int t = blockIdx.x * blockDim.x + threadIdx.x;
    int i = t * DPT;
    if (i + DPT - 1 < E) {
        int c[DPT];
        #pragma unroll
        for (int q = 0; q < DPT / 4; ++q)
            *reinterpret_cast<int4*>(c + q * 4) =
                __ldcs(reinterpret_cast<const int4*>(col + i + q * 4));
        #pragma unroll
        for (int j = 0; j < DPT; ++j) atomicAdd(&g_deg[c[j]], 1.0f);
    } else if (i < E) {
        int iend = min(i + DPT, E);
        for (; i < iend; ++i) atomicAdd(&g_deg[col[i]], 1.0f);
    }
}

// 2) dinv = rsqrt(deg+1); dxv = dinv*x; seed u,t with self-loop; zero A
__global__ void k_dinv(const float* __restrict__ x, int n) {
    int i4 = blockIdx.x * blockDim.x + threadIdx.x;
    int i = i4 * 4;
    if (i + 3 < n) {
        float4 d = *reinterpret_cast<const float4*>(g_deg + i);
        float4 xv = *reinterpret_cast<const float4*>(x + i);
        float4 di, dx;
        di.x = rsqrtf(d.x + 1.0f); di.y = rsqrtf(d.y + 1.0f);
        di.z = rsqrtf(d.z + 1.0f); di.w = rsqrtf(d.w + 1.0f);
        dx.x = di.x * xv.x; dx.y = di.y * xv.y;
        dx.z = di.z * xv.z; dx.w = di.w * xv.w;
        *reinterpret_cast<float4*>(g_dinv + i) = di;
        *reinterpret_cast<float4*>(g_dxv + i)  = dx;
        *reinterpret_cast<float4*>(g_u + i)    = dx;  // self loop: dinv*x
        *reinterpret_cast<float4*>(g_t + i)    = di;  // self loop: dinv
    } else {
        for (; i < n; ++i) {
            float di = rsqrtf(g_deg[i] + 1.0f);
            float dx = di * x[i];
            g_dinv[i] = di; g_dxv[i] = dx; g_u[i] = dx; g_t[i] = di;
        }
    }
    if (i4 == 0) { g_A[0] = 0.0f; g_A[1] = 0.0f; }
}

// 3) edge pass: u[c] += dxv[r]; t[r] += dinv[c]   (16 edges/thread)
#define EPT 16
__global__ void __launch_bounds__(256) k_edge(const int* __restrict__ row,
                                              const int* __restrict__ col, int E) {
    int t = blockIdx.x * blockDim.x + threadIdx.x;
    int i = t * EPT;
    if (i + EPT - 1 < E) {
        int r[EPT], c[EPT];
        #pragma unroll
        for (int q = 0; q < EPT / 4; ++q) {
            *reinterpret_cast<int4*>(r + q * 4) =
                __ldcs(reinterpret_cast<const int4*>(row + i + q * 4));
            *reinterpret_cast<int4*>(c + q * 4) =
                __ldcs(reinterpret_cast<const int4*>(col + i + q * 4));
        }
        float dx[EPT], dc[EPT];
        #pragma unroll
        for (int j = 0; j < EPT; ++j) {
            dx[j] = __ldg(&g_dxv[r[j]]);
            dc[j] = __ldg(&g_dinv[c[j]]);
        }
        #pragma unroll
        for (int j = 0; j < EPT; ++j) {
            atomicAdd(&g_u[c[j]], dx[j]);
            atomicAdd(&g_t[r[j]], dc[j]);
        }
    } else if (i < E) {
        int iend = min(i + EPT, E);
        for (; i < iend; ++i) {
            int r = row[i], c = col[i];
            atomicAdd(&g_u[c], g_dxv[r]);
            atomicAdd(&g_t[r], g_dinv[c]);
        }
    }
}

// 4) A+/A- reduction over nodes (float2/thread, 2x parallelism of before) and
//    re-zero g_deg for the next invocation. Block-level smem reduce ->
//    2 atomics per block. No fence — the kernel boundary orders everything.
__global__ void __launch_bounds__(256) k_sred(int n) {
    __shared__ float sAp[8], sAm[8];
    int tid = threadIdx.x;
    int g = blockIdx.x * blockDim.x + tid;
    int i = g * 2;
    float ap = 0.0f, am = 0.0f;
    if (i + 1 < n) {
        float2 di = *reinterpret_cast<const float2*>(g_dinv + i);
        float2 u  = *reinterpret_cast<const float2*>(g_u + i);
        float2 tt = *reinterpret_cast<const float2*>(g_t + i);
        float s0 = di.x * u.x, w0 = di.x * tt.x;
        float s1 = di.y * u.y, w1 = di.y * tt.y;
        if (s0 > 0.0f) ap += w0 * s0; else am += w0 * s0;
        if (s1 > 0.0f) ap += w1 * s1; else am += w1 * s1;
    } else if (i < n) {
        float di = g_dinv[i];
        float s = di * g_u[i], w = di * g_t[i];
        if (s > 0.0f) ap += w * s; else am += w * s;
    }
    // re-zero g_deg for the next invocation (grid covers MAXN/2 threads)
    if (i + 1 < MAXN)
        *reinterpret_cast<float2*>(g_deg + i) = make_float2(0.f, 0.f);

    #pragma unroll
    for (int off = 16; off; off >>= 1) {
        ap += __shfl_xor_sync(0xffffffffu, ap, off);
        am += __shfl_xor_sync(0xffffffffu, am, off);
    }
    int wid = tid >> 5;
    if ((tid & 31) == 0) { sAp[wid] = ap; sAm[wid] = am; }
    __syncthreads();
    if (tid == 0) {
        float tap = 0.0f, tam = 0.0f;
        #pragma unroll
        for (int wq = 0; wq < 8; ++wq) { tap += sAp[wq]; tam += sAm[wq]; }
        atomicAdd(&g_A[0], tap);
        atomicAdd(&g_A[1], tam);
    }
}

// 5) v[k] = W1k * (W1k>0 ? A+ : A-)   (exact when b1k == 0; fallback otherwise),
//    then out[o] = (1/n)*sum_k v[k]*W2[k,o] + b2[o].  Coalesced over o.
__global__ void __launch_bounds__(256) k_gemv(const float* __restrict__ W1,
                                              const float* __restrict__ b1,
                                              const float* __restrict__ W2,
                                              const float* __restrict__ b2,
                                              float* __restrict__ out,
                                              int n, int od) {
    __shared__ float vs[HID];
    int tid = threadIdx.x;
    if (tid < HID) {
        float Ap = g_A[0];
        float Am = g_A[1];
        float w1k = W1[tid];
        float b1k = b1[tid];
        float v;
        if (b1k == 0.0f) {
            v = w1k * (w1k > 0.0f ? Ap : Am);   // exact ReLU factorization
        } else {
            // generic fallback (never hit with b1 = 0): direct per-node loop
            v = 0.0f;
            for (int q = 0; q < n; ++q) {
                float di = g_dinv[q];
                float s = di * g_u[q], w = di * g_t[q];
                v += w * fmaxf(s * w1k + b1k, 0.0f);
            }
        }
        vs[tid] = v;
    }
    __syncthreads();
    int o = blockIdx.x * blockDim.x + tid;
    if (o >= od) return;
    float inv_n = 1.0f / (float)n;
    float a = 0.0f;
    #pragma unroll 16
    for (int kk = 0; kk < HID; ++kk) {
        a += vs[kk] * __ldg(&W2[kk * od + o]);  // coalesced over o
    }
    out[o] = a * inv_n + b2[o];
}

// ---------------------------------------------------------------------------
extern "C" void kernel_launch(void* const* d_in, const int* in_sizes, int n_in,
                              void* d_out, int out_size) {
    const float* x   = (const float*)d_in[0];   // [N]
    const int*   ei  = (const int*)d_in[1];     // [2, E] row-major
    const float* W1  = (const float*)d_in[2];   // [128]
    const float* b1  = (const float*)d_in[3];   // [128]
    const float* W2  = (const float*)d_in[4];   // [128, OUT]
    const float* b2  = (const float*)d_in[5];   // [OUT]
    float* out = (float*)d_out;

    int N = in_sizes[0];
    int E = in_sizes[1] / 2;
    int OD = in_sizes[5];
    const int* row = ei;
    const int* col = ei + E;

    int tb = 256;
    int ntD = (E + DPT - 1) / DPT;
    k_deg<<<(ntD + tb - 1) / tb, tb>>>(col, E);

    int n4 = (N + 3) / 4;
    k_dinv<<<(n4 + tb - 1) / tb, tb>>>(x, N);

    int ntE = (E + EPT - 1) / EPT;
    k_edge<<<(ntE + tb - 1) / tb, tb>>>(row, col, E);

    int n2 = MAXN / 2;                       // cover MAXN for the g_deg re-zero
    k_sred<<<(n2 + tb - 1) / tb, tb>>>(N);

    k_gemv<<<(OD + tb - 1) / tb, tb>>>(W1, b1, W2, b2, out, N, OD);
}

// round 13
// speedup vs baseline: 1.1191x; 1.0298x over previous
#include <cuda_runtime.h>
#include <cuda_bf16.h>

// Scratch: __device__ globals (no allocations allowed).
// g_deg starts zero (static init) and is re-zeroed by k_sred each call.
#define MAXN 100352   // = 392 * 256, >= 100,000 nodes
#define HID  128

__device__ float g_deg[MAXN];   // edge-degree (zeroed by previous k_sred)
__device__ float g_dinv[MAXN];  // (deg+1)^-1/2
__device__ float g_dxv[MAXN];   // dinv * x
__device__ float g_u[MAXN];     // u[c] = sum dinv[r]*x[r]   (seeded w/ self loop)
__device__ float g_t[MAXN];     // t[r] = sum dinv[c]        (seeded w/ self loop)
__device__ float g_A[2];        // A+ , A-

// ---------------------------------------------------------------------------
// 1) degree scatter over destinations (16 edges/thread, streaming index loads)
#define DPT 16
__global__ void __launch_bounds__(256) k_deg(const int* __restrict__ col, int E) {
    int t = blockIdx.x * blockDim.x + threadIdx.x;
    int i = t * DPT;
    if (i + DPT - 1 < E) {
        int c[DPT];
        #pragma unroll
        for (int q = 0; q < DPT / 4; ++q)
            *reinterpret_cast<int4*>(c + q * 4) =
                __ldcs(reinterpret_cast<const int4*>(col + i + q * 4));
        #pragma unroll
        for (int j = 0; j < DPT; ++j) atomicAdd(&g_deg[c[j]], 1.0f);
    } else if (i < E) {
        int iend = min(i + DPT, E);
        for (; i < iend; ++i) atomicAdd(&g_deg[col[i]], 1.0f);
    }
}

// 2) dinv = rsqrt(deg+1); dxv = dinv*x; seed u,t with self-loop; zero A
//    float2/thread, 196 blocks for latency hiding.
__global__ void __launch_bounds__(256) k_dinv(const float* __restrict__ x, int n) {
    int i2 = blockIdx.x * blockDim.x + threadIdx.x;
    int i = i2 * 2;
    if (i + 1 < n) {
        float2 d  = *reinterpret_cast<const float2*>(g_deg + i);
        float2 xv = *reinterpret_cast<const float2*>(x + i);
        float2 di, dx;
        di.x = rsqrtf(d.x + 1.0f); di.y = rsqrtf(d.y + 1.0f);
        dx.x = di.x * xv.x;        dx.y = di.y * xv.y;
        *reinterpret_cast<float2*>(g_dinv + i) = di;
        *reinterpret_cast<float2*>(g_dxv + i)  = dx;
        *reinterpret_cast<float2*>(g_u + i)    = dx;  // self loop: dinv*x
        *reinterpret_cast<float2*>(g_t + i)    = di;  // self loop: dinv
    } else if (i < n) {
        float di = rsqrtf(g_deg[i] + 1.0f);
        float dx = di * x[i];
        g_dinv[i] = di; g_dxv[i] = dx; g_u[i] = dx; g_t[i] = di;
    }
    if (i2 == 0) { g_A[0] = 0.0f; g_A[1] = 0.0f; }
}

// 3) edge pass: u[c] += dxv[r]; t[r] += dinv[c]   (16 edges/thread)
#define EPT 16
__global__ void __launch_bounds__(256) k_edge(const int* __restrict__ row,
                                              const int* __restrict__ col, int E) {
    int t = blockIdx.x * blockDim.x + threadIdx.x;
    int i = t * EPT;
    if (i + EPT - 1 < E) {
        int r[EPT], c[EPT];
        #pragma unroll
        for (int q = 0; q < EPT / 4; ++q) {
            *reinterpret_cast<int4*>(r + q * 4) =
                __ldcs(reinterpret_cast<const int4*>(row + i + q * 4));
            *reinterpret_cast<int4*>(c + q * 4) =
                __ldcs(reinterpret_cast<const int4*>(col + i + q * 4));
        }
        float dx[EPT], dc[EPT];
        #pragma unroll
        for (int j = 0; j < EPT; ++j) {
            dx[j] = __ldg(&g_dxv[r[j]]);
            dc[j] = __ldg(&g_dinv[c[j]]);
        }
        #pragma unroll
        for (int j = 0; j < EPT; ++j) {
            atomicAdd(&g_u[c[j]], dx[j]);
            atomicAdd(&g_t[r[j]], dc[j]);
        }
    } else if (i < E) {
        int iend = min(i + EPT, E);
        for (; i < iend; ++i) {
            int r = row[i], c = col[i];
            atomicAdd(&g_u[c], g_dxv[r]);
            atomicAdd(&g_t[r], g_dinv[c]);
        }
    }
}

// 4) A+/A- reduction over nodes: 1 element/thread, 392 blocks (grid == MAXN).
//    Also re-zeroes g_deg (1 float/thread, exact cover). Block-level smem
//    reduce -> 2 atomics per block. No fence — kernel boundary orders all.
__global__ void __launch_bounds__(256) k_sred(int n) {
    __shared__ float sAp[8], sAm[8];
    int tid = threadIdx.x;
    int i = blockIdx.x * blockDim.x + tid;    // < MAXN by construction
    float ap = 0.0f, am = 0.0f;
    if (i < n) {
        float di = g_dinv[i];
        float s = di * g_u[i];
        float w = di * g_t[i];
        float ws = w * s;
        if (s > 0.0f) ap = ws; else am = ws;
    }
    g_deg[i] = 0.0f;                          // re-zero for next invocation

    #pragma unroll
    for (int off = 16; off; off >>= 1) {
        ap += __shfl_xor_sync(0xffffffffu, ap, off);
        am += __shfl_xor_sync(0xffffffffu, am, off);
    }
    int wid = tid >> 5;
    if ((tid & 31) == 0) { sAp[wid] = ap; sAm[wid] = am; }
    __syncthreads();
    if (tid == 0) {
        float tap = 0.0f, tam = 0.0f;
        #pragma unroll
        for (int wq = 0; wq < 8; ++wq) { tap += sAp[wq]; tam += sAm[wq]; }
        atomicAdd(&g_A[0], tap);
        atomicAdd(&g_A[1], tam);
    }
}

// 5) v[k] = W1k * (W1k>0 ? A+ : A-)   (exact when b1k == 0; fallback otherwise),
//    then out[o] = (1/n)*sum_k v[k]*W2[k,o] + b2[o].  Coalesced over o.
__global__ void __launch_bounds__(256) k_gemv(const float* __restrict__ W1,
                                              const float* __restrict__ b1,
                                              const float* __restrict__ W2,
                                              const float* __restrict__ b2,
                                              float* __restrict__ out,
                                              int n, int od) {
    __shared__ float vs[HID];
    int tid = threadIdx.x;
    if (tid < HID) {
        float Ap = g_A[0];
        float Am = g_A[1];
        float w1k = W1[tid];
        float b1k = b1[tid];
        float v;
        if (b1k == 0.0f) {
            v = w1k * (w1k > 0.0f ? Ap : Am);   // exact ReLU factorization
        } else {
            // generic fallback (never hit with b1 = 0): direct per-node loop
            v = 0.0f;
            for (int q = 0; q < n; ++q) {
                float di = g_dinv[q];
                float s = di * g_u[q], w = di * g_t[q];
                v += w * fmaxf(s * w1k + b1k, 0.0f);
            }
        }
        vs[tid] = v;
    }
    __syncthreads();
    int o = blockIdx.x * blockDim.x + tid;
    if (o >= od) return;
    float inv_n = 1.0f / (float)n;
    float a = 0.0f;
    #pragma unroll 16
    for (int kk = 0; kk < HID; ++kk) {
        a += vs[kk] * __ldg(&W2[kk * od + o]);  // coalesced over o
    }
    out[o] = a * inv_n + b2[o];
}

// ---------------------------------------------------------------------------
extern "C" void kernel_launch(void* const* d_in, const int* in_sizes, int n_in,
                              void* d_out, int out_size) {
    const float* x   = (const float*)d_in[0];   // [N]
    const int*   ei  = (const int*)d_in[1];     // [2, E] row-major
    const float* W1  = (const float*)d_in[2];   // [128]
    const float* b1  = (const float*)d_in[3];   // [128]
    const float* W2  = (const float*)d_in[4];   // [128, OUT]
    const float* b2  = (const float*)d_in[5];   // [OUT]
    float* out = (float*)d_out;

    int N = in_sizes[0];
    int E = in_sizes[1] / 2;
    int OD = in_sizes[5];
    const int* row = ei;
    const int* col = ei + E;

    int tb = 256;
    int ntD = (E + DPT - 1) / DPT;
    k_deg<<<(ntD + tb - 1) / tb, tb>>>(col, E);

    int n2 = (N + 1) / 2;
    k_dinv<<<(n2 + tb - 1) / tb, tb>>>(x, N);

    int ntE = (E + EPT - 1) / EPT;
    k_edge<<<(ntE + tb - 1) / tb, tb>>>(row, col, E);

    k_sred<<<MAXN / tb, tb>>>(N);               // 392 blocks, exact cover

    k_gemv<<<(OD + tb - 1) / tb, tb>>>(W1, b1, W2, b2, out, N, OD);
}

// round 16
// speedup vs baseline: 1.2115x; 1.0825x over previous
#include <cuda_runtime.h>
#include <cuda_bf16.h>

// Scratch: __device__ globals (no allocations allowed).
// g_deg starts zero (static init) and is re-zeroed by k_sred each call.
#define MAXN 100352   // = 392 * 256, >= 100,000 nodes
#define HID  128

__device__ float g_deg[MAXN];   // edge-degree (zeroed by previous k_sred)
__device__ float g_dinv[MAXN];  // (deg+1)^-1/2
__device__ float g_dxv[MAXN];   // dinv * x
__device__ float g_u[MAXN];     // u[c] = sum dinv[r]*x[r]   (seeded w/ self loop)
__device__ float g_t[MAXN];     // t[r] = sum dinv[c]        (seeded w/ self loop)
__device__ float g_A[2];        // A+ , A-

// NOTE on PDL correctness: no kernel calls cudaTriggerProgrammaticLaunchCompletion.
// The implicit trigger fires at kernel COMPLETION, so every
// cudaGridDependencySynchronize() below observes ALL of the predecessor's
// writes. Dependents still launch early and overlap their independent
// prologues (index streams, GEMV) with the predecessor's execution.

// ---------------------------------------------------------------------------
// 1) degree scatter over destinations (16 edges/thread, streaming index loads)
#define DPT 16
__global__ void __launch_bounds__(256) k_deg(const int* __restrict__ col, int E) {
    int t = blockIdx.x * blockDim.x + threadIdx.x;
    int i = t * DPT;
    if (i + DPT - 1 < E) {
        int c[DPT];
        #pragma unroll
        for (int q = 0; q < DPT / 4; ++q)
            *reinterpret_cast<int4*>(c + q * 4) =
                __ldcs(reinterpret_cast<const int4*>(col + i + q * 4));
        #pragma unroll
        for (int j = 0; j < DPT; ++j) atomicAdd(&g_deg[c[j]], 1.0f);
    } else if (i < E) {
        int iend = min(i + DPT, E);
        for (; i < iend; ++i) atomicAdd(&g_deg[col[i]], 1.0f);
    }
}

// 2) dinv = rsqrt(deg+1); dxv = dinv*x; seed u,t with self-loop; zero A.
//    PDL: x loads in the prologue; g_deg reads after the grid sync.
__global__ void __launch_bounds__(256) k_dinv(const float* __restrict__ x, int n) {
    int i2 = blockIdx.x * blockDim.x + threadIdx.x;
    int i = i2 * 2;
    float2 xv = make_float2(0.f, 0.f);
    bool full = (i + 1 < n);
    if (full)       xv = *reinterpret_cast<const float2*>(x + i);
    else if (i < n) xv.x = x[i];
    cudaGridDependencySynchronize();           // wait for k_deg completion
    if (full) {
        float2 d = *reinterpret_cast<const float2*>(g_deg + i);
        float2 di, dx;
        di.x = rsqrtf(d.x + 1.0f); di.y = rsqrtf(d.y + 1.0f);
        dx.x = di.x * xv.x;        dx.y = di.y * xv.y;
        *reinterpret_cast<float2*>(g_dinv + i) = di;
        *reinterpret_cast<float2*>(g_dxv + i)  = dx;
        *reinterpret_cast<float2*>(g_u + i)    = dx;  // self loop: dinv*x
        *reinterpret_cast<float2*>(g_t + i)    = di;  // self loop: dinv
    } else if (i < n) {
        float di = rsqrtf(g_deg[i] + 1.0f);
        float dx = di * xv.x;
        g_dinv[i] = di; g_dxv[i] = dx; g_u[i] = dx; g_t[i] = di;
    }
    if (i2 == 0) { g_A[0] = 0.0f; g_A[1] = 0.0f; }
}

// 3) edge pass: u[c] += dxv[r]; t[r] += dinv[c]   (16 edges/thread)
//    PDL: the 12.8 MB of index loads run in the prologue, overlapping k_dinv.
#define EPT 16
__global__ void __launch_bounds__(256) k_edge(const int* __restrict__ row,
                                              const int* __restrict__ col, int E) {
    int t = blockIdx.x * blockDim.x + threadIdx.x;
    int i = t * EPT;
    if (i + EPT - 1 < E) {
        int r[EPT], c[EPT];
        #pragma unroll
        for (int q = 0; q < EPT / 4; ++q) {
            *reinterpret_cast<int4*>(r + q * 4) =
                __ldcs(reinterpret_cast<const int4*>(row + i + q * 4));
            *reinterpret_cast<int4*>(c + q * 4) =
                __ldcs(reinterpret_cast<const int4*>(col + i + q * 4));
        }
        cudaGridDependencySynchronize();       // wait for k_dinv completion
        float dx[EPT], dc[EPT];
        #pragma unroll
        for (int j = 0; j < EPT; ++j) {
            dx[j] = __ldg(&g_dxv[r[j]]);
            dc[j] = __ldg(&g_dinv[c[j]]);
        }
        #pragma unroll
        for (int j = 0; j < EPT; ++j) {
            atomicAdd(&g_u[c[j]], dx[j]);
            atomicAdd(&g_t[r[j]], dc[j]);
        }
    } else {
        cudaGridDependencySynchronize();
        if (i < E) {
            int iend = min(i + EPT, E);
            for (; i < iend; ++i) {
                int r = row[i], c = col[i];
                atomicAdd(&g_u[c], g_dxv[r]);
                atomicAdd(&g_t[r], g_dinv[c]);
            }
        }
    }
}

// 4) A+/A- reduction over nodes: 1 element/thread, grid == MAXN.
//    Re-zeroes g_deg. Sync BEFORE any reads — full k_edge visibility.
__global__ void __launch_bounds__(256) k_sred(int n) {
    __shared__ float sAp[8], sAm[8];
    int tid = threadIdx.x;
    int i = blockIdx.x * blockDim.x + tid;     // < MAXN by construction
    cudaGridDependencySynchronize();           // wait for k_edge completion
    float ap = 0.0f, am = 0.0f;
    if (i < n) {
        float di = g_dinv[i];
        float s = di * g_u[i];
        float w = di * g_t[i];
        float ws = w * s;
        if (s > 0.0f) ap = ws; else am = ws;
    }
    g_deg[i] = 0.0f;                           // re-zero for next invocation

    #pragma unroll
    for (int off = 16; off; off >>= 1) {
        ap += __shfl_xor_sync(0xffffffffu, ap, off);
        am += __shfl_xor_sync(0xffffffffu, am, off);
    }
    int wid = tid >> 5;
    if ((tid & 31) == 0) { sAp[wid] = ap; sAm[wid] = am; }
    __syncthreads();
    if (tid == 0) {
        float tap = 0.0f, tam = 0.0f;
        #pragma unroll
        for (int wq = 0; wq < 8; ++wq) { tap += sAp[wq]; tam += sAm[wq]; }
        atomicAdd(&g_A[0], tap);
        atomicAdd(&g_A[1], tam);
    }
}

// 5) out[o] = (P[o]*A+ + M[o]*A-)/n + b2[o], with
//    P[o] = sum_{W1k>0} W1k*W2[k,o],  M[o] = sum_{W1k<0} W1k*W2[k,o].
//    The full GEMV is dependency-free (prologue, overlaps k_sred via PDL);
//    only the 2-float g_A read sits behind the grid sync.
//    Fallback (any b1k != 0): per-node v[k] loop after the sync (never hit here).
__global__ void __launch_bounds__(256) k_gemv(const float* __restrict__ W1,
                                              const float* __restrict__ b1,
                                              const float* __restrict__ W2,
                                              const float* __restrict__ b2,
                                              float* __restrict__ out,
                                              int n, int od) {
    __shared__ float sW1[HID];
    __shared__ int   sFb;
    int tid = threadIdx.x;
    if (tid == 0) sFb = 0;
    __syncthreads();
    if (tid < HID) {
        float w1k = W1[tid];
        sW1[tid] = w1k;
        if (b1[tid] != 0.0f) atomicOr(&sFb, 1);
    }
    __syncthreads();
    int o = blockIdx.x * blockDim.x + tid;
    float P = 0.0f, M = 0.0f;
    float b2o = 0.0f;
    if (o < od) {
        b2o = b2[o];
        #pragma unroll 16
        for (int kk = 0; kk < HID; ++kk) {
            float w1k = sW1[kk];
            float wv = w1k * __ldg(&W2[kk * od + o]);   // coalesced over o
            if (w1k > 0.0f) P += wv; else M += wv;
        }
    }
    cudaGridDependencySynchronize();           // wait for k_sred completion
    float inv_n = 1.0f / (float)n;
    if (sFb == 0) {
        if (o < od) out[o] = (P * g_A[0] + M * g_A[1]) * inv_n + b2o;
    } else {
        // generic-b1 fallback (never hit with b1 = 0)
        __shared__ float vs[HID];
        if (tid < HID) {
            float w1k = sW1[tid];
            float b1k = b1[tid];
            float v = 0.0f;
            for (int q = 0; q < n; ++q) {
                float di = g_dinv[q];
                float s = di * g_u[q], w = di * g_t[q];
                v += w * fmaxf(s * w1k + b1k, 0.0f);
            }
            vs[tid] = v;
        }
        __syncthreads();
        if (o < od) {
            float a = 0.0f;
            for (int kk = 0; kk < HID; ++kk) a += vs[kk] * W2[kk * od + o];
            out[o] = a * inv_n + b2o;
        }
    }
}

// ---------------------------------------------------------------------------
static inline void launch_pdl(const void* fn, int grid, int block, void** args) {
    cudaLaunchConfig_t cfg = {};
    cfg.gridDim = dim3((unsigned)grid, 1, 1);
    cfg.blockDim = dim3((unsigned)block, 1, 1);
    cfg.stream = 0;
    cudaLaunchAttribute at[1];
    at[0].id = cudaLaunchAttributeProgrammaticStreamSerialization;
    at[0].val.programmaticStreamSerializationAllowed = 1;
    cfg.attrs = at;
    cfg.numAttrs = 1;
    cudaLaunchKernelExC(&cfg, fn, args);
}

extern "C" void kernel_launch(void* const* d_in, const int* in_sizes, int n_in,
                              void* d_out, int out_size) {
    const float* x   = (const float*)d_in[0];   // [N]
    const int*   ei  = (const int*)d_in[1];     // [2, E] row-major
    const float* W1  = (const float*)d_in[2];   // [128]
    const float* b1  = (const float*)d_in[3];   // [128]
    const float* W2  = (const float*)d_in[4];   // [128, OUT]
    const float* b2  = (const float*)d_in[5];   // [OUT]
    float* out = (float*)d_out;

    int N = in_sizes[0];
    int E = in_sizes[1] / 2;
    int OD = in_sizes[5];
    const int* row = ei;
    const int* col = ei + E;

    int tb = 256;

    // 1) k_deg (first node — plain launch)
    int ntD = (E + DPT - 1) / DPT;
    k_deg<<<(ntD + tb - 1) / tb, tb>>>(col, E);

    // 2) k_dinv (PDL)
    {
        int n2 = (N + 1) / 2;
        int g = (n2 + tb - 1) / tb;
        void* args[] = { (void*)&x, (void*)&N };
        launch_pdl((const void*)k_dinv, g, tb, args);
    }

    // 3) k_edge (PDL)
    {
        int ntE = (E + EPT - 1) / EPT;
        int g = (ntE + tb - 1) / tb;
        void* args[] = { (void*)&row, (void*)&col, (void*)&E };
        launch_pdl((const void*)k_edge, g, tb, args);
    }

    // 4) k_sred (PDL)
    {
        void* args[] = { (void*)&N };
        launch_pdl((const void*)k_sred, MAXN / tb, tb, args);
    }

    // 5) k_gemv (PDL)
    {
        int g = (OD + tb - 1) / tb;
        void* args[] = { (void*)&W1, (void*)&b1, (void*)&W2, (void*)&b2,
                         (void*)&out, (void*)&N, (void*)&OD };
        launch_pdl((const void*)k_gemv, g, tb, args);
    }
}